// round 12
// baseline (speedup 1.0000x reference)
#include <cuda_runtime.h>
#include <cuda_bf16.h>
#include <cstddef>
#include <cstdint>

// Problem constants
#define BATCH 2
#define SEQ   2048
#define DMODEL 2048
#define NHEADS 16
#define HDIM  128
#define D3    (3 * DMODEL)
#define MROWS (BATCH * SEQ)   // 4096

// ---------------- scratch (no allocations allowed) ----------------
__device__ float g_qkv[(size_t)MROWS * D3];                       // [B*S, 3D]
__device__ float g_Q[(size_t)BATCH * NHEADS * SEQ * HDIM];        // [B,H,S,hd]
__device__ float g_K[(size_t)BATCH * NHEADS * SEQ * HDIM];
__device__ float g_V[(size_t)BATCH * NHEADS * SEQ * HDIM];
__device__ float g_attn[(size_t)MROWS * DMODEL];                  // [B*S, D]
__device__ float g_cos[SEQ * 64];
__device__ float g_sin[SEQ * 64];

// ---------------- helpers ----------------
__device__ __forceinline__ float to_tf32(float x) {
    float r;
    asm("cvt.rna.tf32.f32 %0, %1;" : "=f"(r) : "f"(x));
    return r;
}

// m16n8k8 tf32 warp MMA (base PTX, sm_80+)
__device__ __forceinline__ void mma_tf32(float c[4],
                                         uint32_t a0, uint32_t a1, uint32_t a2, uint32_t a3,
                                         uint32_t b0, uint32_t b1) {
    asm volatile(
        "mma.sync.aligned.m16n8k8.row.col.f32.tf32.tf32.f32 "
        "{%0,%1,%2,%3}, {%4,%5,%6,%7}, {%8,%9}, {%0,%1,%2,%3};"
        : "+f"(c[0]), "+f"(c[1]), "+f"(c[2]), "+f"(c[3])
        : "r"(a0), "r"(a1), "r"(a2), "r"(a3), "r"(b0), "r"(b1));
}

// m16n8k16 bf16 warp MMA (base PTX, sm_80+)
__device__ __forceinline__ void mma_bf16(float c[4],
                                         uint32_t a0, uint32_t a1, uint32_t a2, uint32_t a3,
                                         uint32_t b0, uint32_t b1) {
    asm volatile(
        "mma.sync.aligned.m16n8k16.row.col.f32.bf16.bf16.f32 "
        "{%0,%1,%2,%3}, {%4,%5,%6,%7}, {%8,%9}, {%0,%1,%2,%3};"
        : "+f"(c[0]), "+f"(c[1]), "+f"(c[2]), "+f"(c[3])
        : "r"(a0), "r"(a1), "r"(a2), "r"(a3), "r"(b0), "r"(b1));
}

// ldmatrix x4 (sm_75+ base PTX)
#define LDM4(r0, r1, r2, r3, ptr) \
    asm volatile("ldmatrix.sync.aligned.m8n8.x4.shared.b16 {%0,%1,%2,%3}, [%4];" \
        : "=r"(r0), "=r"(r1), "=r"(r2), "=r"(r3) \
        : "r"((uint32_t)__cvta_generic_to_shared(ptr)))

// pack two fp32 -> bf16x2 reg (lo_elem -> bits[15:0], hi_elem -> bits[31:16])
__device__ __forceinline__ uint32_t pk2(float lo_elem, float hi_elem) {
    uint32_t r;
    asm("cvt.rn.bf16x2.f32 %0, %1, %2;" : "=r"(r) : "f"(hi_elem), "f"(lo_elem));
    return r;
}
__device__ __forceinline__ float bf16rt(float x) {
    return __bfloat162float(__float2bfloat16(x));
}

// ---------------- RoPE table ----------------
__global__ void rope_table_kernel() {
    int s = blockIdx.x;
    int j = threadIdx.x;            // 0..63
    float inv = powf(10000.0f, -(float)j / 64.0f);
    float ang = (float)s * inv;
    g_cos[s * 64 + j] = cosf(ang);
    g_sin[s * 64 + j] = sinf(ang);
}

// ================= tf32 mma.sync GEMM (unchanged, known-good) =================
#define GMM_A_STRIDE 36
#define GMM_B_STRIDE 136
#define GMM_A_FLOATS (128 * GMM_A_STRIDE)   // 4608
#define GMM_B_FLOATS (32 * GMM_B_STRIDE)    // 4352
#define GMM_SMEM_FLOATS (2 * GMM_A_FLOATS + 2 * GMM_B_FLOATS)   // 17920
#define GMM_SMEM_BYTES  (GMM_SMEM_FLOATS * 4)                   // 71680

__global__ __launch_bounds__(256) void tf32_mma_gemm(
    const float* __restrict__ A, const float* __restrict__ B, float* __restrict__ C,
    int M, int N, int K_)
{
    extern __shared__ float sm[];
    float* Asm = sm;                        // [2][128][36]
    float* Bsm = sm + 2 * GMM_A_FLOATS;     // [2][32][136]

    const int tid = threadIdx.x;
    const int wid = tid >> 5, lane = tid & 31;
    const int g = lane >> 2, t = lane & 3;
    const int wm = wid >> 2, wn = wid & 3;
    const int m0 = blockIdx.y * 128, n0 = blockIdx.x * 128;
    const int mbase = wm * 64, nbase = wn * 32;

    float4 apref[4], bpref[4];

    #define LOADG(kt) do { \
        _Pragma("unroll") \
        for (int i = 0; i < 4; i++) { \
            int f4 = tid + i * 256; \
            int r = f4 >> 3, c = (f4 & 7) << 2; \
            apref[i] = *(const float4*)&A[(size_t)(m0 + r) * K_ + (kt) * 32 + c]; \
            int rb = f4 >> 5, cb = (f4 & 31) << 2; \
            bpref[i] = *(const float4*)&B[(size_t)((kt) * 32 + rb) * N + n0 + cb]; \
        } \
    } while (0)

    #define STORES(buf) do { \
        _Pragma("unroll") \
        for (int i = 0; i < 4; i++) { \
            int f4 = tid + i * 256; \
            int r = f4 >> 3, c = (f4 & 7) << 2; \
            float4 v = apref[i]; \
            v.x = to_tf32(v.x); v.y = to_tf32(v.y); v.z = to_tf32(v.z); v.w = to_tf32(v.w); \
            *(float4*)&Asm[(buf) * GMM_A_FLOATS + r * GMM_A_STRIDE + c] = v; \
            int rb = f4 >> 5, cb = (f4 & 31) << 2; \
            float4 w = bpref[i]; \
            w.x = to_tf32(w.x); w.y = to_tf32(w.y); w.z = to_tf32(w.z); w.w = to_tf32(w.w); \
            *(float4*)&Bsm[(buf) * GMM_B_FLOATS + rb * GMM_B_STRIDE + cb] = w; \
        } \
    } while (0)

    float acc[4][4][4];
    #pragma unroll
    for (int mf = 0; mf < 4; mf++)
        #pragma unroll
        for (int nf = 0; nf < 4; nf++)
            #pragma unroll
            for (int q = 0; q < 4; q++) acc[mf][nf][q] = 0.0f;

    const int KT = K_ / 32;
    LOADG(0);
    STORES(0);
    __syncthreads();

    for (int kt = 0; kt < KT; kt++) {
        const int buf = kt & 1;
        if (kt + 1 < KT) LOADG(kt + 1);

        const float* Ab = &Asm[buf * GMM_A_FLOATS];
        const float* Bb = &Bsm[buf * GMM_B_FLOATS];
        #pragma unroll
        for (int ks = 0; ks < 4; ks++) {
            const int k = ks * 8;
            uint32_t af[4][4];
            #pragma unroll
            for (int mf = 0; mf < 4; mf++) {
                const int row = mbase + mf * 16 + g;
                af[mf][0] = __float_as_uint(Ab[row * GMM_A_STRIDE + k + t]);
                af[mf][1] = __float_as_uint(Ab[(row + 8) * GMM_A_STRIDE + k + t]);
                af[mf][2] = __float_as_uint(Ab[row * GMM_A_STRIDE + k + t + 4]);
                af[mf][3] = __float_as_uint(Ab[(row + 8) * GMM_A_STRIDE + k + t + 4]);
            }
            uint32_t bfr[4][2];
            #pragma unroll
            for (int nf = 0; nf < 4; nf++) {
                const int col = nbase + nf * 8 + g;
                bfr[nf][0] = __float_as_uint(Bb[(k + t) * GMM_B_STRIDE + col]);
                bfr[nf][1] = __float_as_uint(Bb[(k + t + 4) * GMM_B_STRIDE + col]);
            }
            #pragma unroll
            for (int mf = 0; mf < 4; mf++)
                #pragma unroll
                for (int nf = 0; nf < 4; nf++)
                    mma_tf32(acc[mf][nf], af[mf][0], af[mf][1], af[mf][2], af[mf][3],
                             bfr[nf][0], bfr[nf][1]);
        }

        if (kt + 1 < KT) {
            STORES(buf ^ 1);
            __syncthreads();
        }
    }

    #pragma unroll
    for (int mf = 0; mf < 4; mf++) {
        #pragma unroll
        for (int nf = 0; nf < 4; nf++) {
            const int row = m0 + mbase + mf * 16 + g;
            const int col = n0 + nbase + nf * 8 + 2 * t;
            *(float2*)&C[(size_t)row * N + col] =
                make_float2(acc[mf][nf][0], acc[mf][nf][1]);
            *(float2*)&C[(size_t)(row + 8) * N + col] =
                make_float2(acc[mf][nf][2], acc[mf][nf][3]);
        }
    }
    #undef LOADG
    #undef STORES
}

// ---------------- RoPE + split + transpose ----------------
__global__ __launch_bounds__(256) void rope_split_kernel(
    const float* __restrict__ qkv,
    float* __restrict__ Q, float* __restrict__ K, float* __restrict__ V)
{
    int bs = blockIdx.x;
    int b = bs / SEQ, s = bs % SEQ;
    const float* row = qkv + (size_t)bs * D3;

    for (int e = threadIdx.x; e < DMODEL; e += 256) {
        int h = e >> 7, d = e & 127, j = d & 63;
        float c  = g_cos[s * 64 + j];
        float sn = g_sin[s * 64 + j];
        float qv = row[e];
        float kv = row[DMODEL + e];
        float vv = row[2 * DMODEL + e];
        int po = (d < 64) ? (e + 64) : (e - 64);
        float sgn = (d < 64) ? -1.0f : 1.0f;
        float qp = row[po];
        float kp = row[DMODEL + po];
        float qo = qv * c + sgn * qp * sn;
        float ko = kv * c + sgn * kp * sn;
        size_t oidx = ((size_t)(b * NHEADS + h) * SEQ + s) * HDIM + d;
        Q[oidx] = qo;
        K[oidx] = ko;
        V[oidx] = vv;
    }
}

// ============ bf16 split-precision flash attention (mma.sync + ldmatrix) ============
// Same structure as R10 (passing), but ALL fragment loads go through
// ldmatrix.m8n8.x4 instead of scalar LDS.32 (~4x fewer load instructions).
// Q/K rows: 128 d-elems, stride QST=136 elems (272B = 16 mod 128 -> ldmatrix
// row phases conflict-free). VT rows: 64 kv-elems, stride VST=72 (144B, same).
#define QST 136
#define VST 72
#define S_QHI 0
#define S_QLO (128 * QST)                        // 17408
#define S_KB  (2 * 128 * QST)                    // 34816
#define S_KHI(b) (S_KB + (b) * 2 * 64 * QST)
#define S_KLO(b) (S_KHI(b) + 64 * QST)
#define S_VB  (S_KB + 2 * 2 * 64 * QST)          // 69632
#define S_VHI(b) (S_VB + (b) * 2 * 128 * VST)
#define S_VLO(b) (S_VHI(b) + 128 * VST)
#define ATT_ELEMS (S_VB + 2 * 2 * 128 * VST)     // 106496 bf16
#define ATT_BYTES (ATT_ELEMS * 2)                // 212992

__global__ __launch_bounds__(256, 1) void attn_bf16_kernel(
    const float* __restrict__ Qg, const float* __restrict__ Kg,
    const float* __restrict__ Vg, float* __restrict__ Og)
{
    extern __shared__ __nv_bfloat16 smh[];
    const int tid = threadIdx.x;
    const int w = tid >> 5, lane = tid & 31;
    const int g = lane >> 2, t = lane & 3;
    const int qb = w * 16;
    const int bh = blockIdx.y;
    const int s0 = blockIdx.x * 128;
    const float* Qb = Qg + (size_t)bh * SEQ * HDIM;
    const float* Kb = Kg + (size_t)bh * SEQ * HDIM;
    const float* Vb = Vg + (size_t)bh * SEQ * HDIM;
    const float SCL2E = 0.08838834764831845f * 1.4426950408889634f; // 1/sqrt(128)*log2e

    // per-lane ldmatrix row offsets (element units)
    // A-frag (Q, 16 rows x k16): lanes 0-15 -> rows, k+0; lanes 16-31 -> rows, k+8
    const int qa_off = (qb + (lane & 15)) * QST + ((lane & 16) >> 1);
    // B-frag pair (K/VT, two n8 blocks x k16):
    // lanes 0-7: blk0 rows k+0; 8-15: blk0 rows k+8; 16-23: blk1 rows k+0; 24-31: blk1 k+8
    const int bp_row = (lane & 7) + ((lane >> 4) << 3);
    const int kb_off = bp_row * QST + (lane & 8);
    const int vb_off = bp_row * VST + (lane & 8);

    // ---- load Q tile (128 x 128), hi/lo bf16 split ----
    #pragma unroll
    for (int i = 0; i < 16; i++) {
        int f4 = tid + i * 256;                 // 0..4095
        int r = f4 >> 5, c4 = (f4 & 31) << 2;
        float4 v = *(const float4*)&Qb[(size_t)(s0 + r) * HDIM + c4];
        __nv_bfloat16 h0 = __float2bfloat16(v.x), h1 = __float2bfloat16(v.y);
        __nv_bfloat16 h2 = __float2bfloat16(v.z), h3 = __float2bfloat16(v.w);
        *(__nv_bfloat162*)&smh[S_QHI + r * QST + c4]     = __halves2bfloat162(h0, h1);
        *(__nv_bfloat162*)&smh[S_QHI + r * QST + c4 + 2] = __halves2bfloat162(h2, h3);
        __nv_bfloat16 l0 = __float2bfloat16(v.x - __bfloat162float(h0));
        __nv_bfloat16 l1 = __float2bfloat16(v.y - __bfloat162float(h1));
        __nv_bfloat16 l2 = __float2bfloat16(v.z - __bfloat162float(h2));
        __nv_bfloat16 l3 = __float2bfloat16(v.w - __bfloat162float(h3));
        *(__nv_bfloat162*)&smh[S_QLO + r * QST + c4]     = __halves2bfloat162(l0, l1);
        *(__nv_bfloat162*)&smh[S_QLO + r * QST + c4 + 2] = __halves2bfloat162(l2, l3);
    }

    // ---- tile loader: K [64][128] split + V transposed to [d][kv] split ----
    #define LOAD_TILE(kt, b) do { \
        const int ks0_ = (kt) * 64; \
        _Pragma("unroll") \
        for (int i = 0; i < 8; i++) { \
            int f4 = tid + i * 256; \
            int r = f4 >> 5, c4 = (f4 & 31) << 2; \
            float4 v = *(const float4*)&Kb[(size_t)(ks0_ + r) * HDIM + c4]; \
            __nv_bfloat16 h0 = __float2bfloat16(v.x), h1 = __float2bfloat16(v.y); \
            __nv_bfloat16 h2 = __float2bfloat16(v.z), h3 = __float2bfloat16(v.w); \
            *(__nv_bfloat162*)&smh[S_KHI(b) + r * QST + c4]     = __halves2bfloat162(h0, h1); \
            *(__nv_bfloat162*)&smh[S_KHI(b) + r * QST + c4 + 2] = __halves2bfloat162(h2, h3); \
            __nv_bfloat16 l0 = __float2bfloat16(v.x - __bfloat162float(h0)); \
            __nv_bfloat16 l1 = __float2bfloat16(v.y - __bfloat162float(h1)); \
            __nv_bfloat16 l2 = __float2bfloat16(v.z - __bfloat162float(h2)); \
            __nv_bfloat16 l3 = __float2bfloat16(v.w - __bfloat162float(h3)); \
            *(__nv_bfloat162*)&smh[S_KLO(b) + r * QST + c4]     = __halves2bfloat162(l0, l1); \
            *(__nv_bfloat162*)&smh[S_KLO(b) + r * QST + c4 + 2] = __halves2bfloat162(l2, l3); \
        } \
        _Pragma("unroll") \
        for (int it = 0; it < 32; it++) { \
            int kv = w + 8 * (it >> 2); \
            int d  = ((it & 3) << 5) + lane; \
            float v = Vb[(size_t)(ks0_ + kv) * HDIM + d]; \
            __nv_bfloat16 hv = __float2bfloat16(v); \
            smh[S_VHI(b) + d * VST + kv] = hv; \
            smh[S_VLO(b) + d * VST + kv] = __float2bfloat16(v - __bfloat162float(hv)); \
        } \
    } while (0)

    LOAD_TILE(0, 0);
    __syncthreads();

    float m0 = -1e30f, m1 = -1e30f, l0 = 0.0f, l1 = 0.0f;
    float acc[16][4];
    #pragma unroll
    for (int nf = 0; nf < 16; nf++)
        #pragma unroll
        for (int q = 0; q < 4; q++) acc[nf][q] = 0.0f;

    for (int kt = 0; kt < SEQ / 64; kt++) {
        const int buf = kt & 1;
        if (kt + 1 < SEQ / 64) LOAD_TILE(kt + 1, buf ^ 1);

        // ---- S = Q K^T : 3-mma bf16 via ldmatrix, 16q x 64kv per warp ----
        float sfr[8][4];
        #pragma unroll
        for (int nf = 0; nf < 8; nf++)
            #pragma unroll
            for (int q = 0; q < 4; q++) sfr[nf][q] = 0.0f;

        #pragma unroll
        for (int ks = 0; ks < 8; ks++) {
            uint32_t ah0, ah1, ah2, ah3, al0, al1, al2, al3;
            LDM4(ah0, ah1, ah2, ah3, &smh[S_QHI + qa_off + ks * 16]);
            LDM4(al0, al1, al2, al3, &smh[S_QLO + qa_off + ks * 16]);
            #pragma unroll
            for (int nfp = 0; nfp < 4; nfp++) {
                uint32_t kh0, kh1, kh2, kh3, kl0, kl1, kl2, kl3;
                LDM4(kh0, kh1, kh2, kh3,
                     &smh[S_KHI(buf) + nfp * 16 * QST + kb_off + ks * 16]);
                LDM4(kl0, kl1, kl2, kl3,
                     &smh[S_KLO(buf) + nfp * 16 * QST + kb_off + ks * 16]);
                mma_bf16(sfr[2 * nfp],     ah0, ah1, ah2, ah3, kh0, kh1);
                mma_bf16(sfr[2 * nfp],     ah0, ah1, ah2, ah3, kl0, kl1);
                mma_bf16(sfr[2 * nfp],     al0, al1, al2, al3, kh0, kh1);
                mma_bf16(sfr[2 * nfp + 1], ah0, ah1, ah2, ah3, kh2, kh3);
                mma_bf16(sfr[2 * nfp + 1], ah0, ah1, ah2, ah3, kl2, kl3);
                mma_bf16(sfr[2 * nfp + 1], al0, al1, al2, al3, kh2, kh3);
            }
        }

        // ---- warp-local online softmax (log2 domain) ----
        #pragma unroll
        for (int nf = 0; nf < 8; nf++)
            #pragma unroll
            for (int q = 0; q < 4; q++) sfr[nf][q] *= SCL2E;

        float mx0 = -1e30f, mx1 = -1e30f;
        #pragma unroll
        for (int nf = 0; nf < 8; nf++) {
            mx0 = fmaxf(mx0, fmaxf(sfr[nf][0], sfr[nf][1]));
            mx1 = fmaxf(mx1, fmaxf(sfr[nf][2], sfr[nf][3]));
        }
        mx0 = fmaxf(mx0, __shfl_xor_sync(0xffffffffu, mx0, 1));
        mx0 = fmaxf(mx0, __shfl_xor_sync(0xffffffffu, mx0, 2));
        mx1 = fmaxf(mx1, __shfl_xor_sync(0xffffffffu, mx1, 1));
        mx1 = fmaxf(mx1, __shfl_xor_sync(0xffffffffu, mx1, 2));

        float mn0 = fmaxf(m0, mx0), mn1 = fmaxf(m1, mx1);
        float corr0 = exp2f(m0 - mn0), corr1 = exp2f(m1 - mn1);
        m0 = mn0; m1 = mn1;

        float sum0 = 0.0f, sum1 = 0.0f;
        #pragma unroll
        for (int nf = 0; nf < 8; nf++) {
            sfr[nf][0] = exp2f(sfr[nf][0] - mn0);
            sfr[nf][1] = exp2f(sfr[nf][1] - mn0);
            sfr[nf][2] = exp2f(sfr[nf][2] - mn1);
            sfr[nf][3] = exp2f(sfr[nf][3] - mn1);
            sum0 += sfr[nf][0] + sfr[nf][1];
            sum1 += sfr[nf][2] + sfr[nf][3];
        }
        sum0 += __shfl_xor_sync(0xffffffffu, sum0, 1);
        sum0 += __shfl_xor_sync(0xffffffffu, sum0, 2);
        sum1 += __shfl_xor_sync(0xffffffffu, sum1, 1);
        sum1 += __shfl_xor_sync(0xffffffffu, sum1, 2);
        l0 = l0 * corr0 + sum0;
        l1 = l1 * corr1 + sum1;

        #pragma unroll
        for (int nf = 0; nf < 16; nf++) {
            acc[nf][0] *= corr0; acc[nf][1] *= corr0;
            acc[nf][2] *= corr1; acc[nf][3] *= corr1;
        }

        // ---- O += P V : 3-mma bf16, P packed from C-frags, V via ldmatrix ----
        #pragma unroll
        for (int ks2 = 0; ks2 < 4; ks2++) {
            const float* p0 = sfr[2 * ks2];
            const float* p1 = sfr[2 * ks2 + 1];
            uint32_t ah0 = pk2(p0[0], p0[1]);
            uint32_t ah1 = pk2(p0[2], p0[3]);
            uint32_t ah2 = pk2(p1[0], p1[1]);
            uint32_t ah3 = pk2(p1[2], p1[3]);
            uint32_t al0 = pk2(p0[0] - bf16rt(p0[0]), p0[1] - bf16rt(p0[1]));
            uint32_t al1 = pk2(p0[2] - bf16rt(p0[2]), p0[3] - bf16rt(p0[3]));
            uint32_t al2 = pk2(p1[0] - bf16rt(p1[0]), p1[1] - bf16rt(p1[1]));
            uint32_t al3 = pk2(p1[2] - bf16rt(p1[2]), p1[3] - bf16rt(p1[3]));
            #pragma unroll
            for (int nfp = 0; nfp < 8; nfp++) {
                uint32_t vh0, vh1, vh2, vh3, vl0, vl1, vl2, vl3;
                LDM4(vh0, vh1, vh2, vh3,
                     &smh[S_VHI(buf) + nfp * 16 * VST + vb_off + ks2 * 16]);
                LDM4(vl0, vl1, vl2, vl3,
                     &smh[S_VLO(buf) + nfp * 16 * VST + vb_off + ks2 * 16]);
                mma_bf16(acc[2 * nfp],     ah0, ah1, ah2, ah3, vh0, vh1);
                mma_bf16(acc[2 * nfp],     ah0, ah1, ah2, ah3, vl0, vl1);
                mma_bf16(acc[2 * nfp],     al0, al1, al2, al3, vh0, vh1);
                mma_bf16(acc[2 * nfp + 1], ah0, ah1, ah2, ah3, vh2, vh3);
                mma_bf16(acc[2 * nfp + 1], ah0, ah1, ah2, ah3, vl2, vl3);
                mma_bf16(acc[2 * nfp + 1], al0, al1, al2, al3, vh2, vh3);
            }
        }
        __syncthreads();
    }

    // ---- epilogue: normalize, write [B*S, D] (col = h*128 + d) ----
    const float rl0 = 1.0f / l0, rl1 = 1.0f / l1;
    const int b = bh >> 4, h = bh & 15;
    const size_t base0 = (size_t)(b * SEQ + s0 + qb + g) * DMODEL + h * HDIM;
    const size_t base1 = (size_t)(b * SEQ + s0 + qb + g + 8) * DMODEL + h * HDIM;
    #pragma unroll
    for (int nf = 0; nf < 16; nf++) {
        const int colb = nf * 8 + 2 * t;
        *(float2*)&Og[base0 + colb] = make_float2(acc[nf][0] * rl0, acc[nf][1] * rl0);
        *(float2*)&Og[base1 + colb] = make_float2(acc[nf][2] * rl1, acc[nf][3] * rl1);
    }
    #undef LOAD_TILE
}

// ---------------- launch ----------------
extern "C" void kernel_launch(void* const* d_in, const int* in_sizes, int n_in,
                              void* d_out, int out_size)
{
    const float* x     = (const float*)d_in[0];
    const float* w_qkv = (const float*)d_in[1];
    const float* w_out = (const float*)d_in[2];
    float* out = (float*)d_out;

    float *qkv, *Q, *K, *V, *attn;
    cudaGetSymbolAddress((void**)&qkv,  g_qkv);
    cudaGetSymbolAddress((void**)&Q,    g_Q);
    cudaGetSymbolAddress((void**)&K,    g_K);
    cudaGetSymbolAddress((void**)&V,    g_V);
    cudaGetSymbolAddress((void**)&attn, g_attn);

    cudaFuncSetAttribute(tf32_mma_gemm, cudaFuncAttributeMaxDynamicSharedMemorySize,
                         GMM_SMEM_BYTES);
    cudaFuncSetAttribute(attn_bf16_kernel, cudaFuncAttributeMaxDynamicSharedMemorySize,
                         ATT_BYTES);

    rope_table_kernel<<<SEQ, 64>>>();
    // qkv = x @ w_qkv   [4096,2048]x[2048,6144]  (tf32 mma.sync)
    tf32_mma_gemm<<<dim3(D3 / 128, MROWS / 128), 256, GMM_SMEM_BYTES>>>(
        x, w_qkv, qkv, MROWS, D3, DMODEL);
    // rope + split
    rope_split_kernel<<<MROWS, 256>>>(qkv, Q, K, V);
    // attention (bf16 split-precision flash, ldmatrix fragment loads)
    attn_bf16_kernel<<<dim3(SEQ / 128, BATCH * NHEADS), 256, ATT_BYTES>>>(Q, K, V, attn);
    // out = attn @ w_out  [4096,2048]x[2048,2048]  (tf32 mma.sync)
    tf32_mma_gemm<<<dim3(DMODEL / 128, MROWS / 128), 256, GMM_SMEM_BYTES>>>(
        attn, w_out, out, MROWS, DMODEL, DMODEL);
}

// round 14
// speedup vs baseline: 1.7910x; 1.7910x over previous
#include <cuda_runtime.h>
#include <cuda_bf16.h>
#include <cuda_fp16.h>
#include <cstddef>
#include <cstdint>

// Problem constants
#define BATCH 2
#define SEQ   2048
#define DMODEL 2048
#define NHEADS 16
#define HDIM  128
#define D3    (3 * DMODEL)
#define MROWS (BATCH * SEQ)   // 4096

// ---------------- scratch (no allocations allowed) ----------------
__device__ float g_qkv[(size_t)MROWS * D3];                       // [B*S, 3D]
__device__ float g_Q[(size_t)BATCH * NHEADS * SEQ * HDIM];        // [B,H,S,hd]
__device__ float g_K[(size_t)BATCH * NHEADS * SEQ * HDIM];
__device__ float g_V[(size_t)BATCH * NHEADS * SEQ * HDIM];
__device__ float g_attn[(size_t)MROWS * DMODEL];                  // [B*S, D]
__device__ float g_cos[SEQ * 64];
__device__ float g_sin[SEQ * 64];
__device__ __half g_wqkvT[(size_t)D3 * DMODEL];                   // w_qkv^T fp16 [N][K]
__device__ __half g_woutT[(size_t)DMODEL * DMODEL];               // w_out^T fp16 [N][K]

// ---------------- helpers ----------------
// m16n8k16 fp16 warp MMA, fp32 accumulate (base PTX, sm_80+)
__device__ __forceinline__ void mma_fp16(float c[4],
                                         uint32_t a0, uint32_t a1, uint32_t a2, uint32_t a3,
                                         uint32_t b0, uint32_t b1) {
    asm volatile(
        "mma.sync.aligned.m16n8k16.row.col.f32.f16.f16.f32 "
        "{%0,%1,%2,%3}, {%4,%5,%6,%7}, {%8,%9}, {%0,%1,%2,%3};"
        : "+f"(c[0]), "+f"(c[1]), "+f"(c[2]), "+f"(c[3])
        : "r"(a0), "r"(a1), "r"(a2), "r"(a3), "r"(b0), "r"(b1));
}

// m16n8k16 bf16 warp MMA (base PTX, sm_80+)
__device__ __forceinline__ void mma_bf16(float c[4],
                                         uint32_t a0, uint32_t a1, uint32_t a2, uint32_t a3,
                                         uint32_t b0, uint32_t b1) {
    asm volatile(
        "mma.sync.aligned.m16n8k16.row.col.f32.bf16.bf16.f32 "
        "{%0,%1,%2,%3}, {%4,%5,%6,%7}, {%8,%9}, {%0,%1,%2,%3};"
        : "+f"(c[0]), "+f"(c[1]), "+f"(c[2]), "+f"(c[3])
        : "r"(a0), "r"(a1), "r"(a2), "r"(a3), "r"(b0), "r"(b1));
}

// pack two fp32 -> bf16x2 reg (lo_elem -> bits[15:0], hi_elem -> bits[31:16])
__device__ __forceinline__ uint32_t pk2(float lo_elem, float hi_elem) {
    uint32_t r;
    asm("cvt.rn.bf16x2.f32 %0, %1, %2;" : "=r"(r) : "f"(hi_elem), "f"(lo_elem));
    return r;
}
__device__ __forceinline__ float bf16rt(float x) {
    return __bfloat162float(__float2bfloat16(x));
}

// ---------------- RoPE table ----------------
__global__ void rope_table_kernel() {
    int s = blockIdx.x;
    int j = threadIdx.x;            // 0..63
    float inv = powf(10000.0f, -(float)j / 64.0f);
    float ang = (float)s * inv;
    g_cos[s * 64 + j] = cosf(ang);
    g_sin[s * 64 + j] = sinf(ang);
}

// ---------------- weight transpose: W[K][N] fp32 -> WT[N][K] fp16 ----------------
__global__ __launch_bounds__(256) void transpose_fp16_kernel(
    const float* __restrict__ W, __half* __restrict__ WT, int K_, int N)
{
    __shared__ float t[32][33];
    const int tx = threadIdx.x, ty = threadIdx.y;   // (32, 8)
    const int n0 = blockIdx.x * 32, k0 = blockIdx.y * 32;
    #pragma unroll
    for (int j = 0; j < 4; j++)
        t[ty + 8 * j][tx] = W[(size_t)(k0 + ty + 8 * j) * N + n0 + tx];
    __syncthreads();
    #pragma unroll
    for (int j = 0; j < 4; j++)
        WT[(size_t)(n0 + ty + 8 * j) * K_ + k0 + tx] = __float2half(t[tx][ty + 8 * j]);
}

// ================= fp16 m16n8k16 GEMM: C[M,N] = A[M,K] * B[K,N] =================
// B pre-transposed to fp16 [N][K]. Tile 128x128, BK=32, 256 threads (8 warps 2x4),
// warp tile 64x32 (4x4 frags). Smem fp16, row stride 40 elems (20 words):
// frag loads hit banks (20g + t) mod 32 -> all 32 distinct, conflict-free.
#define GF_AST 40
#define GF_ELEMS (128 * GF_AST)            // 5120 halfs per tile buffer

__global__ __launch_bounds__(256) void fp16_mma_gemm(
    const float* __restrict__ A, const __half* __restrict__ Bt, float* __restrict__ C,
    int M, int N, int K_)
{
    __shared__ __half Asm[2][GF_ELEMS];
    __shared__ __half Bsm[2][GF_ELEMS];

    const int tid = threadIdx.x;
    const int wid = tid >> 5, lane = tid & 31;
    const int g = lane >> 2, t = lane & 3;
    const int wm = wid >> 2, wn = wid & 3;
    const int m0 = blockIdx.y * 128, n0 = blockIdx.x * 128;
    const int mbase = wm * 64, nbase = wn * 32;

    float4 apref[4];
    uint4  bpref[2];

    #define LOADG(kt) do { \
        _Pragma("unroll") \
        for (int i = 0; i < 4; i++) { \
            int f4 = tid + i * 256; \
            int r = f4 >> 3, c = (f4 & 7) << 2; \
            apref[i] = *(const float4*)&A[(size_t)(m0 + r) * K_ + (kt) * 32 + c]; \
        } \
        _Pragma("unroll") \
        for (int i = 0; i < 2; i++) { \
            int idx = tid + i * 256; \
            int r = idx >> 2, c8 = (idx & 3) << 3; \
            bpref[i] = *(const uint4*)&Bt[(size_t)(n0 + r) * K_ + (kt) * 32 + c8]; \
        } \
    } while (0)

    #define STORES(buf) do { \
        _Pragma("unroll") \
        for (int i = 0; i < 4; i++) { \
            int f4 = tid + i * 256; \
            int r = f4 >> 3, c = (f4 & 7) << 2; \
            __half2 p0 = __floats2half2_rn(apref[i].x, apref[i].y); \
            __half2 p1 = __floats2half2_rn(apref[i].z, apref[i].w); \
            uint2 pk; pk.x = *(uint32_t*)&p0; pk.y = *(uint32_t*)&p1; \
            *(uint2*)&Asm[buf][r * GF_AST + c] = pk; \
        } \
        _Pragma("unroll") \
        for (int i = 0; i < 2; i++) { \
            int idx = tid + i * 256; \
            int r = idx >> 2, c8 = (idx & 3) << 3; \
            *(uint4*)&Bsm[buf][r * GF_AST + c8] = bpref[i]; \
        } \
    } while (0)

    float acc[4][4][4];
    #pragma unroll
    for (int mf = 0; mf < 4; mf++)
        #pragma unroll
        for (int nf = 0; nf < 4; nf++)
            #pragma unroll
            for (int q = 0; q < 4; q++) acc[mf][nf][q] = 0.0f;

    const int KT = K_ / 32;
    LOADG(0);
    STORES(0);
    __syncthreads();

    for (int kt = 0; kt < KT; kt++) {
        const int buf = kt & 1;
        if (kt + 1 < KT) LOADG(kt + 1);

        const uint32_t* Aw = (const uint32_t*)Asm[buf];
        const uint32_t* Bw = (const uint32_t*)Bsm[buf];
        #pragma unroll
        for (int ks = 0; ks < 2; ks++) {
            const int kw = ks * 8;          // word offset of k16 step
            uint32_t af[4][4];
            #pragma unroll
            for (int mf = 0; mf < 4; mf++) {
                const int row = mbase + mf * 16 + g;
                const int base = row * 20 + kw + t;
                af[mf][0] = Aw[base];
                af[mf][1] = Aw[base + 8 * 20];
                af[mf][2] = Aw[base + 4];
                af[mf][3] = Aw[base + 8 * 20 + 4];
            }
            uint32_t bfr[4][2];
            #pragma unroll
            for (int nf = 0; nf < 4; nf++) {
                const int col = nbase + nf * 8 + g;
                const int base = col * 20 + kw + t;
                bfr[nf][0] = Bw[base];
                bfr[nf][1] = Bw[base + 4];
            }
            #pragma unroll
            for (int mf = 0; mf < 4; mf++)
                #pragma unroll
                for (int nf = 0; nf < 4; nf++)
                    mma_fp16(acc[mf][nf], af[mf][0], af[mf][1], af[mf][2], af[mf][3],
                             bfr[nf][0], bfr[nf][1]);
        }

        if (kt + 1 < KT) {
            STORES(buf ^ 1);
            __syncthreads();
        }
    }

    #pragma unroll
    for (int mf = 0; mf < 4; mf++) {
        #pragma unroll
        for (int nf = 0; nf < 4; nf++) {
            const int row = m0 + mbase + mf * 16 + g;
            const int col = n0 + nbase + nf * 8 + 2 * t;
            *(float2*)&C[(size_t)row * N + col] =
                make_float2(acc[mf][nf][0], acc[mf][nf][1]);
            *(float2*)&C[(size_t)(row + 8) * N + col] =
                make_float2(acc[mf][nf][2], acc[mf][nf][3]);
        }
    }
    #undef LOADG
    #undef STORES
}

// ---------------- RoPE + split + transpose ----------------
__global__ __launch_bounds__(256) void rope_split_kernel(
    const float* __restrict__ qkv,
    float* __restrict__ Q, float* __restrict__ K, float* __restrict__ V)
{
    int bs = blockIdx.x;
    int b = bs / SEQ, s = bs % SEQ;
    const float* row = qkv + (size_t)bs * D3;

    for (int e = threadIdx.x; e < DMODEL; e += 256) {
        int h = e >> 7, d = e & 127, j = d & 63;
        float c  = g_cos[s * 64 + j];
        float sn = g_sin[s * 64 + j];
        float qv = row[e];
        float kv = row[DMODEL + e];
        float vv = row[2 * DMODEL + e];
        int po = (d < 64) ? (e + 64) : (e - 64);
        float sgn = (d < 64) ? -1.0f : 1.0f;
        float qp = row[po];
        float kp = row[DMODEL + po];
        float qo = qv * c + sgn * qp * sn;
        float ko = kv * c + sgn * kp * sn;
        size_t oidx = ((size_t)(b * NHEADS + h) * SEQ + s) * HDIM + d;
        Q[oidx] = qo;
        K[oidx] = ko;
        V[oidx] = vv;
    }
}

// ============ bf16 split-precision flash attention (exact R10, known-good) ============
// q-tile 128, kv-tile 64, 256 threads = 8 warps; warp w owns q rows w*16..w*16+15
// and ALL 64 kv columns -> warp-local softmax, P stays in registers.
// QK^T: 3-mma bf16 hi/lo split.  PV: 3-mma bf16 (P split in regs, V split in smem).
// Q/K rows: 128 d-elems, stride QST=136.  VT rows: 64 kv-elems, stride VST=72.
#define QST 136
#define VST 72
#define S_QHI 0
#define S_QLO (128 * QST)                        // 17408
#define S_KB  (2 * 128 * QST)                    // 34816
#define S_KHI(b) (S_KB + (b) * 2 * 64 * QST)
#define S_KLO(b) (S_KHI(b) + 64 * QST)
#define S_VB  (S_KB + 2 * 2 * 64 * QST)          // 69632
#define S_VHI(b) (S_VB + (b) * 2 * 128 * VST)
#define S_VLO(b) (S_VHI(b) + 128 * VST)
#define ATT_ELEMS (S_VB + 2 * 2 * 128 * VST)     // 106496 bf16
#define ATT_BYTES (ATT_ELEMS * 2)                // 212992

__global__ __launch_bounds__(256, 1) void attn_bf16_kernel(
    const float* __restrict__ Qg, const float* __restrict__ Kg,
    const float* __restrict__ Vg, float* __restrict__ Og)
{
    extern __shared__ __nv_bfloat16 smh[];
    const int tid = threadIdx.x;
    const int w = tid >> 5, lane = tid & 31;
    const int g = lane >> 2, t = lane & 3;
    const int qb = w * 16;
    const int bh = blockIdx.y;
    const int s0 = blockIdx.x * 128;
    const float* Qb = Qg + (size_t)bh * SEQ * HDIM;
    const float* Kb = Kg + (size_t)bh * SEQ * HDIM;
    const float* Vb = Vg + (size_t)bh * SEQ * HDIM;
    const float SCL2E = 0.08838834764831845f * 1.4426950408889634f; // 1/sqrt(128)*log2e

    // ---- load Q tile (128 x 128), hi/lo bf16 split ----
    #pragma unroll
    for (int i = 0; i < 16; i++) {
        int f4 = tid + i * 256;                 // 0..4095
        int r = f4 >> 5, c4 = (f4 & 31) << 2;
        float4 v = *(const float4*)&Qb[(size_t)(s0 + r) * HDIM + c4];
        __nv_bfloat16 h0 = __float2bfloat16(v.x), h1 = __float2bfloat16(v.y);
        __nv_bfloat16 h2 = __float2bfloat16(v.z), h3 = __float2bfloat16(v.w);
        *(__nv_bfloat162*)&smh[S_QHI + r * QST + c4]     = __halves2bfloat162(h0, h1);
        *(__nv_bfloat162*)&smh[S_QHI + r * QST + c4 + 2] = __halves2bfloat162(h2, h3);
        __nv_bfloat16 l0 = __float2bfloat16(v.x - __bfloat162float(h0));
        __nv_bfloat16 l1 = __float2bfloat16(v.y - __bfloat162float(h1));
        __nv_bfloat16 l2 = __float2bfloat16(v.z - __bfloat162float(h2));
        __nv_bfloat16 l3 = __float2bfloat16(v.w - __bfloat162float(h3));
        *(__nv_bfloat162*)&smh[S_QLO + r * QST + c4]     = __halves2bfloat162(l0, l1);
        *(__nv_bfloat162*)&smh[S_QLO + r * QST + c4 + 2] = __halves2bfloat162(l2, l3);
    }

    // ---- tile loader: K [64][128] split + V transposed to [d][kv] split ----
    #define LOAD_TILE(kt, b) do { \
        const int ks0_ = (kt) * 64; \
        _Pragma("unroll") \
        for (int i = 0; i < 8; i++) { \
            int f4 = tid + i * 256; \
            int r = f4 >> 5, c4 = (f4 & 31) << 2; \
            float4 v = *(const float4*)&Kb[(size_t)(ks0_ + r) * HDIM + c4]; \
            __nv_bfloat16 h0 = __float2bfloat16(v.x), h1 = __float2bfloat16(v.y); \
            __nv_bfloat16 h2 = __float2bfloat16(v.z), h3 = __float2bfloat16(v.w); \
            *(__nv_bfloat162*)&smh[S_KHI(b) + r * QST + c4]     = __halves2bfloat162(h0, h1); \
            *(__nv_bfloat162*)&smh[S_KHI(b) + r * QST + c4 + 2] = __halves2bfloat162(h2, h3); \
            __nv_bfloat16 l0 = __float2bfloat16(v.x - __bfloat162float(h0)); \
            __nv_bfloat16 l1 = __float2bfloat16(v.y - __bfloat162float(h1)); \
            __nv_bfloat16 l2 = __float2bfloat16(v.z - __bfloat162float(h2)); \
            __nv_bfloat16 l3 = __float2bfloat16(v.w - __bfloat162float(h3)); \
            *(__nv_bfloat162*)&smh[S_KLO(b) + r * QST + c4]     = __halves2bfloat162(l0, l1); \
            *(__nv_bfloat162*)&smh[S_KLO(b) + r * QST + c4 + 2] = __halves2bfloat162(l2, l3); \
        } \
        _Pragma("unroll") \
        for (int it = 0; it < 32; it++) { \
            int kv = w + 8 * (it >> 2); \
            int d  = ((it & 3) << 5) + lane; \
            float v = Vb[(size_t)(ks0_ + kv) * HDIM + d]; \
            __nv_bfloat16 hv = __float2bfloat16(v); \
            smh[S_VHI(b) + d * VST + kv] = hv; \
            smh[S_VLO(b) + d * VST + kv] = __float2bfloat16(v - __bfloat162float(hv)); \
        } \
    } while (0)

    LOAD_TILE(0, 0);
    __syncthreads();

    float m0 = -1e30f, m1 = -1e30f, l0 = 0.0f, l1 = 0.0f;
    float acc[16][4];
    #pragma unroll
    for (int nf = 0; nf < 16; nf++)
        #pragma unroll
        for (int q = 0; q < 4; q++) acc[nf][q] = 0.0f;

    const uint32_t* QhiW = (const uint32_t*)(smh + S_QHI);
    const uint32_t* QloW = (const uint32_t*)(smh + S_QLO);

    for (int kt = 0; kt < SEQ / 64; kt++) {
        const int buf = kt & 1;
        if (kt + 1 < SEQ / 64) LOAD_TILE(kt + 1, buf ^ 1);

        const uint32_t* KhiW = (const uint32_t*)(smh + S_KHI(buf));
        const uint32_t* KloW = (const uint32_t*)(smh + S_KLO(buf));
        const uint32_t* VhiW = (const uint32_t*)(smh + S_VHI(buf));
        const uint32_t* VloW = (const uint32_t*)(smh + S_VLO(buf));

        // ---- S = Q K^T : 3-mma bf16, 16q x 64kv per warp ----
        float sfr[8][4];
        #pragma unroll
        for (int nf = 0; nf < 8; nf++)
            #pragma unroll
            for (int q = 0; q < 4; q++) sfr[nf][q] = 0.0f;

        #pragma unroll
        for (int ks = 0; ks < 8; ks++) {
            const int aw = (qb + g) * 68 + ks * 8 + t;
            const int aw8 = aw + 8 * 68;
            uint32_t ah0 = QhiW[aw],     ah1 = QhiW[aw8];
            uint32_t ah2 = QhiW[aw + 4], ah3 = QhiW[aw8 + 4];
            uint32_t al0 = QloW[aw],     al1 = QloW[aw8];
            uint32_t al2 = QloW[aw + 4], al3 = QloW[aw8 + 4];
            #pragma unroll
            for (int nf = 0; nf < 8; nf++) {
                const int bw = (nf * 8 + g) * 68 + ks * 8 + t;
                uint32_t bh0 = KhiW[bw], bh1 = KhiW[bw + 4];
                uint32_t bl0 = KloW[bw], bl1 = KloW[bw + 4];
                mma_bf16(sfr[nf], ah0, ah1, ah2, ah3, bh0, bh1);
                mma_bf16(sfr[nf], ah0, ah1, ah2, ah3, bl0, bl1);
                mma_bf16(sfr[nf], al0, al1, al2, al3, bh0, bh1);
            }
        }

        // ---- warp-local online softmax (log2 domain) ----
        #pragma unroll
        for (int nf = 0; nf < 8; nf++)
            #pragma unroll
            for (int q = 0; q < 4; q++) sfr[nf][q] *= SCL2E;

        float mx0 = -1e30f, mx1 = -1e30f;
        #pragma unroll
        for (int nf = 0; nf < 8; nf++) {
            mx0 = fmaxf(mx0, fmaxf(sfr[nf][0], sfr[nf][1]));
            mx1 = fmaxf(mx1, fmaxf(sfr[nf][2], sfr[nf][3]));
        }
        mx0 = fmaxf(mx0, __shfl_xor_sync(0xffffffffu, mx0, 1));
        mx0 = fmaxf(mx0, __shfl_xor_sync(0xffffffffu, mx0, 2));
        mx1 = fmaxf(mx1, __shfl_xor_sync(0xffffffffu, mx1, 1));
        mx1 = fmaxf(mx1, __shfl_xor_sync(0xffffffffu, mx1, 2));

        float mn0 = fmaxf(m0, mx0), mn1 = fmaxf(m1, mx1);
        float corr0 = exp2f(m0 - mn0), corr1 = exp2f(m1 - mn1);
        m0 = mn0; m1 = mn1;

        float sum0 = 0.0f, sum1 = 0.0f;
        #pragma unroll
        for (int nf = 0; nf < 8; nf++) {
            sfr[nf][0] = exp2f(sfr[nf][0] - mn0);
            sfr[nf][1] = exp2f(sfr[nf][1] - mn0);
            sfr[nf][2] = exp2f(sfr[nf][2] - mn1);
            sfr[nf][3] = exp2f(sfr[nf][3] - mn1);
            sum0 += sfr[nf][0] + sfr[nf][1];
            sum1 += sfr[nf][2] + sfr[nf][3];
        }
        sum0 += __shfl_xor_sync(0xffffffffu, sum0, 1);
        sum0 += __shfl_xor_sync(0xffffffffu, sum0, 2);
        sum1 += __shfl_xor_sync(0xffffffffu, sum1, 1);
        sum1 += __shfl_xor_sync(0xffffffffu, sum1, 2);
        l0 = l0 * corr0 + sum0;
        l1 = l1 * corr1 + sum1;

        #pragma unroll
        for (int nf = 0; nf < 16; nf++) {
            acc[nf][0] *= corr0; acc[nf][1] *= corr0;
            acc[nf][2] *= corr1; acc[nf][3] *= corr1;
        }

        // ---- O += P V : 3-mma bf16, P packed straight from C-frags ----
        #pragma unroll
        for (int ks2 = 0; ks2 < 4; ks2++) {
            const float* p0 = sfr[2 * ks2];
            const float* p1 = sfr[2 * ks2 + 1];
            uint32_t ah0 = pk2(p0[0], p0[1]);
            uint32_t ah1 = pk2(p0[2], p0[3]);
            uint32_t ah2 = pk2(p1[0], p1[1]);
            uint32_t ah3 = pk2(p1[2], p1[3]);
            uint32_t al0 = pk2(p0[0] - bf16rt(p0[0]), p0[1] - bf16rt(p0[1]));
            uint32_t al1 = pk2(p0[2] - bf16rt(p0[2]), p0[3] - bf16rt(p0[3]));
            uint32_t al2 = pk2(p1[0] - bf16rt(p1[0]), p1[1] - bf16rt(p1[1]));
            uint32_t al3 = pk2(p1[2] - bf16rt(p1[2]), p1[3] - bf16rt(p1[3]));
            #pragma unroll
            for (int nf = 0; nf < 16; nf++) {
                const int bw = (nf * 8 + g) * 36 + ks2 * 8 + t;
                uint32_t bh0 = VhiW[bw], bh1 = VhiW[bw + 4];
                uint32_t bl0 = VloW[bw], bl1 = VloW[bw + 4];
                mma_bf16(acc[nf], ah0, ah1, ah2, ah3, bh0, bh1);
                mma_bf16(acc[nf], ah0, ah1, ah2, ah3, bl0, bl1);
                mma_bf16(acc[nf], al0, al1, al2, al3, bh0, bh1);
            }
        }
        __syncthreads();
    }

    // ---- epilogue: normalize, write [B*S, D] (col = h*128 + d) ----
    const float rl0 = 1.0f / l0, rl1 = 1.0f / l1;
    const int b = bh >> 4, h = bh & 15;
    const size_t base0 = (size_t)(b * SEQ + s0 + qb + g) * DMODEL + h * HDIM;
    const size_t base1 = (size_t)(b * SEQ + s0 + qb + g + 8) * DMODEL + h * HDIM;
    #pragma unroll
    for (int nf = 0; nf < 16; nf++) {
        const int colb = nf * 8 + 2 * t;
        *(float2*)&Og[base0 + colb] = make_float2(acc[nf][0] * rl0, acc[nf][1] * rl0);
        *(float2*)&Og[base1 + colb] = make_float2(acc[nf][2] * rl1, acc[nf][3] * rl1);
    }
    #undef LOAD_TILE
}

// ---------------- launch ----------------
extern "C" void kernel_launch(void* const* d_in, const int* in_sizes, int n_in,
                              void* d_out, int out_size)
{
    const float* x     = (const float*)d_in[0];
    const float* w_qkv = (const float*)d_in[1];
    const float* w_out = (const float*)d_in[2];
    float* out = (float*)d_out;

    float *qkv, *Q, *K, *V, *attn;
    __half *wqkvT, *woutT;
    cudaGetSymbolAddress((void**)&qkv,   g_qkv);
    cudaGetSymbolAddress((void**)&Q,     g_Q);
    cudaGetSymbolAddress((void**)&K,     g_K);
    cudaGetSymbolAddress((void**)&V,     g_V);
    cudaGetSymbolAddress((void**)&attn,  g_attn);
    cudaGetSymbolAddress((void**)&wqkvT, g_wqkvT);
    cudaGetSymbolAddress((void**)&woutT, g_woutT);

    cudaFuncSetAttribute(attn_bf16_kernel, cudaFuncAttributeMaxDynamicSharedMemorySize,
                         ATT_BYTES);

    rope_table_kernel<<<SEQ, 64>>>();
    // pre-transpose weights to fp16 [N][K]
    transpose_fp16_kernel<<<dim3(D3 / 32, DMODEL / 32), dim3(32, 8)>>>(
        w_qkv, wqkvT, DMODEL, D3);
    transpose_fp16_kernel<<<dim3(DMODEL / 32, DMODEL / 32), dim3(32, 8)>>>(
        w_out, woutT, DMODEL, DMODEL);
    // qkv = x @ w_qkv   [4096,2048]x[2048,6144]  (fp16 m16n8k16 mma.sync)
    fp16_mma_gemm<<<dim3(D3 / 128, MROWS / 128), 256>>>(
        x, wqkvT, qkv, MROWS, D3, DMODEL);
    // rope + split
    rope_split_kernel<<<MROWS, 256>>>(qkv, Q, K, V);
    // attention (bf16 split-precision flash, R10 known-good)
    attn_bf16_kernel<<<dim3(SEQ / 128, BATCH * NHEADS), 256, ATT_BYTES>>>(Q, K, V, attn);
    // out = attn @ w_out  [4096,2048]x[2048,2048]  (fp16 m16n8k16 mma.sync)
    fp16_mma_gemm<<<dim3(DMODEL / 128, MROWS / 128), 256>>>(
        attn, woutT, out, MROWS, DMODEL, DMODEL);
}

// round 15
// speedup vs baseline: 2.7703x; 1.5468x over previous
#include <cuda_runtime.h>
#include <cuda_bf16.h>
#include <cuda_fp16.h>
#include <cstddef>
#include <cstdint>

// Problem constants
#define BATCH 2
#define SEQ   2048
#define DMODEL 2048
#define NHEADS 16
#define HDIM  128
#define D3    (3 * DMODEL)
#define MROWS (BATCH * SEQ)   // 4096

// ---------------- scratch (no allocations allowed) ----------------
__device__ float g_qkv[(size_t)MROWS * D3];                       // [B*S, 3D]
__device__ float g_Q[(size_t)BATCH * NHEADS * SEQ * HDIM];        // [B,H,S,hd]
__device__ float g_K[(size_t)BATCH * NHEADS * SEQ * HDIM];
__device__ float g_V[(size_t)BATCH * NHEADS * SEQ * HDIM];
__device__ float g_attn[(size_t)MROWS * DMODEL];                  // [B*S, D]
__device__ float g_cos[SEQ * 64];
__device__ float g_sin[SEQ * 64];
__device__ __half g_wqkvT[(size_t)D3 * DMODEL];                   // w_qkv^T fp16 [N][K]
__device__ __half g_woutT[(size_t)DMODEL * DMODEL];               // w_out^T fp16 [N][K]

// ---------------- helpers ----------------
// m16n8k16 fp16 warp MMA, fp32 accumulate (base PTX, sm_80+)
__device__ __forceinline__ void mma_fp16(float c[4],
                                         uint32_t a0, uint32_t a1, uint32_t a2, uint32_t a3,
                                         uint32_t b0, uint32_t b1) {
    asm volatile(
        "mma.sync.aligned.m16n8k16.row.col.f32.f16.f16.f32 "
        "{%0,%1,%2,%3}, {%4,%5,%6,%7}, {%8,%9}, {%0,%1,%2,%3};"
        : "+f"(c[0]), "+f"(c[1]), "+f"(c[2]), "+f"(c[3])
        : "r"(a0), "r"(a1), "r"(a2), "r"(a3), "r"(b0), "r"(b1));
}

// pack two fp32 -> fp16x2 reg (lo_elem -> bits[15:0], hi_elem -> bits[31:16])
__device__ __forceinline__ uint32_t pk2h(float lo_elem, float hi_elem) {
    uint32_t r;
    asm("cvt.rn.f16x2.f32 %0, %1, %2;" : "=r"(r) : "f"(hi_elem), "f"(lo_elem));
    return r;
}

// ---------------- RoPE table ----------------
__global__ void rope_table_kernel() {
    int s = blockIdx.x;
    int j = threadIdx.x;            // 0..63
    float inv = powf(10000.0f, -(float)j / 64.0f);
    float ang = (float)s * inv;
    g_cos[s * 64 + j] = cosf(ang);
    g_sin[s * 64 + j] = sinf(ang);
}

// ---------------- weight transpose: W[K][N] fp32 -> WT[N][K] fp16 ----------------
__global__ __launch_bounds__(256) void transpose_fp16_kernel(
    const float* __restrict__ W, __half* __restrict__ WT, int K_, int N)
{
    __shared__ float t[32][33];
    const int tx = threadIdx.x, ty = threadIdx.y;   // (32, 8)
    const int n0 = blockIdx.x * 32, k0 = blockIdx.y * 32;
    #pragma unroll
    for (int j = 0; j < 4; j++)
        t[ty + 8 * j][tx] = W[(size_t)(k0 + ty + 8 * j) * N + n0 + tx];
    __syncthreads();
    #pragma unroll
    for (int j = 0; j < 4; j++)
        WT[(size_t)(n0 + ty + 8 * j) * K_ + k0 + tx] = __float2half(t[tx][ty + 8 * j]);
}

// ================= fp16 m16n8k16 GEMM: C[M,N] = A[M,K] * B[K,N] =================
// B pre-transposed to fp16 [N][K]. Tile 128x128, BK=32, 256 threads (8 warps 2x4),
// warp tile 64x32 (4x4 frags). Smem fp16, row stride 40 elems (20 words).
// __launch_bounds__(256, 2): cap regs at 128 -> 2 CTAs/SM (16 warps, latency hiding).
#define GF_AST 40
#define GF_ELEMS (128 * GF_AST)            // 5120 halfs per tile buffer

__global__ __launch_bounds__(256, 2) void fp16_mma_gemm(
    const float* __restrict__ A, const __half* __restrict__ Bt, float* __restrict__ C,
    int M, int N, int K_)
{
    __shared__ __half Asm[2][GF_ELEMS];
    __shared__ __half Bsm[2][GF_ELEMS];

    const int tid = threadIdx.x;
    const int wid = tid >> 5, lane = tid & 31;
    const int g = lane >> 2, t = lane & 3;
    const int wm = wid >> 2, wn = wid & 3;
    const int m0 = blockIdx.y * 128, n0 = blockIdx.x * 128;
    const int mbase = wm * 64, nbase = wn * 32;

    float4 apref[4];
    uint4  bpref[2];

    #define LOADG(kt) do { \
        _Pragma("unroll") \
        for (int i = 0; i < 4; i++) { \
            int f4 = tid + i * 256; \
            int r = f4 >> 3, c = (f4 & 7) << 2; \
            apref[i] = *(const float4*)&A[(size_t)(m0 + r) * K_ + (kt) * 32 + c]; \
        } \
        _Pragma("unroll") \
        for (int i = 0; i < 2; i++) { \
            int idx = tid + i * 256; \
            int r = idx >> 2, c8 = (idx & 3) << 3; \
            bpref[i] = *(const uint4*)&Bt[(size_t)(n0 + r) * K_ + (kt) * 32 + c8]; \
        } \
    } while (0)

    #define STORES(buf) do { \
        _Pragma("unroll") \
        for (int i = 0; i < 4; i++) { \
            int f4 = tid + i * 256; \
            int r = f4 >> 3, c = (f4 & 7) << 2; \
            __half2 p0 = __floats2half2_rn(apref[i].x, apref[i].y); \
            __half2 p1 = __floats2half2_rn(apref[i].z, apref[i].w); \
            uint2 pk; pk.x = *(uint32_t*)&p0; pk.y = *(uint32_t*)&p1; \
            *(uint2*)&Asm[buf][r * GF_AST + c] = pk; \
        } \
        _Pragma("unroll") \
        for (int i = 0; i < 2; i++) { \
            int idx = tid + i * 256; \
            int r = idx >> 2, c8 = (idx & 3) << 3; \
            *(uint4*)&Bsm[buf][r * GF_AST + c8] = bpref[i]; \
        } \
    } while (0)

    float acc[4][4][4];
    #pragma unroll
    for (int mf = 0; mf < 4; mf++)
        #pragma unroll
        for (int nf = 0; nf < 4; nf++)
            #pragma unroll
            for (int q = 0; q < 4; q++) acc[mf][nf][q] = 0.0f;

    const int KT = K_ / 32;
    LOADG(0);
    STORES(0);
    __syncthreads();

    for (int kt = 0; kt < KT; kt++) {
        const int buf = kt & 1;
        if (kt + 1 < KT) LOADG(kt + 1);

        const uint32_t* Aw = (const uint32_t*)Asm[buf];
        const uint32_t* Bw = (const uint32_t*)Bsm[buf];
        #pragma unroll
        for (int ks = 0; ks < 2; ks++) {
            const int kw = ks * 8;          // word offset of k16 step
            uint32_t af[4][4];
            #pragma unroll
            for (int mf = 0; mf < 4; mf++) {
                const int row = mbase + mf * 16 + g;
                const int base = row * 20 + kw + t;
                af[mf][0] = Aw[base];
                af[mf][1] = Aw[base + 8 * 20];
                af[mf][2] = Aw[base + 4];
                af[mf][3] = Aw[base + 8 * 20 + 4];
            }
            uint32_t bfr[4][2];
            #pragma unroll
            for (int nf = 0; nf < 4; nf++) {
                const int col = nbase + nf * 8 + g;
                const int base = col * 20 + kw + t;
                bfr[nf][0] = Bw[base];
                bfr[nf][1] = Bw[base + 4];
            }
            #pragma unroll
            for (int mf = 0; mf < 4; mf++)
                #pragma unroll
                for (int nf = 0; nf < 4; nf++)
                    mma_fp16(acc[mf][nf], af[mf][0], af[mf][1], af[mf][2], af[mf][3],
                             bfr[nf][0], bfr[nf][1]);
        }

        if (kt + 1 < KT) {
            STORES(buf ^ 1);
            __syncthreads();
        }
    }

    #pragma unroll
    for (int mf = 0; mf < 4; mf++) {
        #pragma unroll
        for (int nf = 0; nf < 4; nf++) {
            const int row = m0 + mbase + mf * 16 + g;
            const int col = n0 + nbase + nf * 8 + 2 * t;
            *(float2*)&C[(size_t)row * N + col] =
                make_float2(acc[mf][nf][0], acc[mf][nf][1]);
            *(float2*)&C[(size_t)(row + 8) * N + col] =
                make_float2(acc[mf][nf][2], acc[mf][nf][3]);
        }
    }
    #undef LOADG
    #undef STORES
}

// ---------------- RoPE + split + transpose ----------------
__global__ __launch_bounds__(256) void rope_split_kernel(
    const float* __restrict__ qkv,
    float* __restrict__ Q, float* __restrict__ K, float* __restrict__ V)
{
    int bs = blockIdx.x;
    int b = bs / SEQ, s = bs % SEQ;
    const float* row = qkv + (size_t)bs * D3;

    for (int e = threadIdx.x; e < DMODEL; e += 256) {
        int h = e >> 7, d = e & 127, j = d & 63;
        float c  = g_cos[s * 64 + j];
        float sn = g_sin[s * 64 + j];
        float qv = row[e];
        float kv = row[DMODEL + e];
        float vv = row[2 * DMODEL + e];
        int po = (d < 64) ? (e + 64) : (e - 64);
        float sgn = (d < 64) ? -1.0f : 1.0f;
        float qp = row[po];
        float kp = row[DMODEL + po];
        float qo = qv * c + sgn * qp * sn;
        float ko = kv * c + sgn * kp * sn;
        size_t oidx = ((size_t)(b * NHEADS + h) * SEQ + s) * HDIM + d;
        Q[oidx] = qo;
        K[oidx] = ko;
        V[oidx] = vv;
    }
}

// ============ fp16 flash attention (mma.sync m16n8k16) ============
// q-tile 128, kv-tile 64, 256 threads = 8 warps; warp w owns q rows w*16..w*16+15
// and ALL 64 kv columns -> warp-local softmax, P stays in registers.
// QK^T: 2-mma fp16 (Q hi/lo split, K plain fp16) -> scaled-logit error ~1e-4.
// PV:   1-mma fp16 (P plain from C-frags, V plain fp16).
// Q/K rows: 128 d-elems, stride QST=136 (68 words = 4 mod 32, conflict-free).
// VT rows: 64 kv-elems, stride VST=72 (36 words, same property). K/VT double-buffered.
#define QST 136
#define VST 72
#define S_QHI 0
#define S_QLO (128 * QST)                        // 17408
#define S_KB  (2 * 128 * QST)                    // 34816
#define S_K(b)  (S_KB + (b) * 64 * QST)
#define S_VTB (S_KB + 2 * 64 * QST)              // 52224
#define S_VT(b) (S_VTB + (b) * 128 * VST)
#define ATT_ELEMS (S_VTB + 2 * 128 * VST)        // 70656 halfs
#define ATT_BYTES (ATT_ELEMS * 2)                // 141312

__global__ __launch_bounds__(256, 1) void attn_fp16_kernel(
    const float* __restrict__ Qg, const float* __restrict__ Kg,
    const float* __restrict__ Vg, float* __restrict__ Og)
{
    extern __shared__ __half smh[];
    const int tid = threadIdx.x;
    const int w = tid >> 5, lane = tid & 31;
    const int g = lane >> 2, t = lane & 3;
    const int qb = w * 16;
    const int bh = blockIdx.y;
    const int s0 = blockIdx.x * 128;
    const float* Qb = Qg + (size_t)bh * SEQ * HDIM;
    const float* Kb = Kg + (size_t)bh * SEQ * HDIM;
    const float* Vb = Vg + (size_t)bh * SEQ * HDIM;
    const float SCL2E = 0.08838834764831845f * 1.4426950408889634f; // 1/sqrt(128)*log2e

    // ---- load Q tile (128 x 128), hi/lo fp16 split ----
    #pragma unroll
    for (int i = 0; i < 16; i++) {
        int f4 = tid + i * 256;                 // 0..4095
        int r = f4 >> 5, c4 = (f4 & 31) << 2;
        float4 v = *(const float4*)&Qb[(size_t)(s0 + r) * HDIM + c4];
        __half h0 = __float2half(v.x), h1 = __float2half(v.y);
        __half h2 = __float2half(v.z), h3 = __float2half(v.w);
        *(__half2*)&smh[S_QHI + r * QST + c4]     = __halves2half2(h0, h1);
        *(__half2*)&smh[S_QHI + r * QST + c4 + 2] = __halves2half2(h2, h3);
        __half l0 = __float2half(v.x - __half2float(h0));
        __half l1 = __float2half(v.y - __half2float(h1));
        __half l2 = __float2half(v.z - __half2float(h2));
        __half l3 = __float2half(v.w - __half2float(h3));
        *(__half2*)&smh[S_QLO + r * QST + c4]     = __halves2half2(l0, l1);
        *(__half2*)&smh[S_QLO + r * QST + c4 + 2] = __halves2half2(l2, l3);
    }

    // ---- tile loader: K [64][128] plain fp16 + V transposed to [d][kv] plain fp16 ----
    #define LOAD_TILE(kt, b) do { \
        const int ks0_ = (kt) * 64; \
        _Pragma("unroll") \
        for (int i = 0; i < 8; i++) { \
            int f4 = tid + i * 256; \
            int r = f4 >> 5, c4 = (f4 & 31) << 2; \
            float4 v = *(const float4*)&Kb[(size_t)(ks0_ + r) * HDIM + c4]; \
            *(__half2*)&smh[S_K(b) + r * QST + c4]     = __floats2half2_rn(v.x, v.y); \
            *(__half2*)&smh[S_K(b) + r * QST + c4 + 2] = __floats2half2_rn(v.z, v.w); \
        } \
        _Pragma("unroll") \
        for (int it = 0; it < 32; it++) { \
            int kv = w + 8 * (it >> 2); \
            int d  = ((it & 3) << 5) + lane; \
            float v = Vb[(size_t)(ks0_ + kv) * HDIM + d]; \
            smh[S_VT(b) + d * VST + kv] = __float2half(v); \
        } \
    } while (0)

    LOAD_TILE(0, 0);
    __syncthreads();

    float m0 = -1e30f, m1 = -1e30f, l0 = 0.0f, l1 = 0.0f;
    float acc[16][4];
    #pragma unroll
    for (int nf = 0; nf < 16; nf++)
        #pragma unroll
        for (int q = 0; q < 4; q++) acc[nf][q] = 0.0f;

    const uint32_t* QhiW = (const uint32_t*)(smh + S_QHI);
    const uint32_t* QloW = (const uint32_t*)(smh + S_QLO);

    for (int kt = 0; kt < SEQ / 64; kt++) {
        const int buf = kt & 1;
        if (kt + 1 < SEQ / 64) LOAD_TILE(kt + 1, buf ^ 1);

        const uint32_t* Kw  = (const uint32_t*)(smh + S_K(buf));
        const uint32_t* VtW = (const uint32_t*)(smh + S_VT(buf));

        // ---- S = Q K^T : 2-mma fp16 (Q split, K plain), 16q x 64kv per warp ----
        float sfr[8][4];
        #pragma unroll
        for (int nf = 0; nf < 8; nf++)
            #pragma unroll
            for (int q = 0; q < 4; q++) sfr[nf][q] = 0.0f;

        #pragma unroll
        for (int ks = 0; ks < 8; ks++) {
            const int aw = (qb + g) * 68 + ks * 8 + t;
            const int aw8 = aw + 8 * 68;
            uint32_t ah0 = QhiW[aw],     ah1 = QhiW[aw8];
            uint32_t ah2 = QhiW[aw + 4], ah3 = QhiW[aw8 + 4];
            uint32_t al0 = QloW[aw],     al1 = QloW[aw8];
            uint32_t al2 = QloW[aw + 4], al3 = QloW[aw8 + 4];
            #pragma unroll
            for (int nf = 0; nf < 8; nf++) {
                const int bw = (nf * 8 + g) * 68 + ks * 8 + t;
                uint32_t b0 = Kw[bw], b1 = Kw[bw + 4];
                mma_fp16(sfr[nf], ah0, ah1, ah2, ah3, b0, b1);
                mma_fp16(sfr[nf], al0, al1, al2, al3, b0, b1);
            }
        }

        // ---- warp-local online softmax (log2 domain) ----
        #pragma unroll
        for (int nf = 0; nf < 8; nf++)
            #pragma unroll
            for (int q = 0; q < 4; q++) sfr[nf][q] *= SCL2E;

        float mx0 = -1e30f, mx1 = -1e30f;
        #pragma unroll
        for (int nf = 0; nf < 8; nf++) {
            mx0 = fmaxf(mx0, fmaxf(sfr[nf][0], sfr[nf][1]));
            mx1 = fmaxf(mx1, fmaxf(sfr[nf][2], sfr[nf][3]));
        }
        mx0 = fmaxf(mx0, __shfl_xor_sync(0xffffffffu, mx0, 1));
        mx0 = fmaxf(mx0, __shfl_xor_sync(0xffffffffu, mx0, 2));
        mx1 = fmaxf(mx1, __shfl_xor_sync(0xffffffffu, mx1, 1));
        mx1 = fmaxf(mx1, __shfl_xor_sync(0xffffffffu, mx1, 2));

        float mn0 = fmaxf(m0, mx0), mn1 = fmaxf(m1, mx1);
        float corr0 = exp2f(m0 - mn0), corr1 = exp2f(m1 - mn1);
        m0 = mn0; m1 = mn1;

        float sum0 = 0.0f, sum1 = 0.0f;
        #pragma unroll
        for (int nf = 0; nf < 8; nf++) {
            sfr[nf][0] = exp2f(sfr[nf][0] - mn0);
            sfr[nf][1] = exp2f(sfr[nf][1] - mn0);
            sfr[nf][2] = exp2f(sfr[nf][2] - mn1);
            sfr[nf][3] = exp2f(sfr[nf][3] - mn1);
            sum0 += sfr[nf][0] + sfr[nf][1];
            sum1 += sfr[nf][2] + sfr[nf][3];
        }
        sum0 += __shfl_xor_sync(0xffffffffu, sum0, 1);
        sum0 += __shfl_xor_sync(0xffffffffu, sum0, 2);
        sum1 += __shfl_xor_sync(0xffffffffu, sum1, 1);
        sum1 += __shfl_xor_sync(0xffffffffu, sum1, 2);
        l0 = l0 * corr0 + sum0;
        l1 = l1 * corr1 + sum1;

        #pragma unroll
        for (int nf = 0; nf < 16; nf++) {
            acc[nf][0] *= corr0; acc[nf][1] *= corr0;
            acc[nf][2] *= corr1; acc[nf][3] *= corr1;
        }

        // ---- O += P V : 1-mma fp16, P packed straight from C-frags ----
        #pragma unroll
        for (int ks2 = 0; ks2 < 4; ks2++) {
            const float* p0 = sfr[2 * ks2];
            const float* p1 = sfr[2 * ks2 + 1];
            uint32_t a0 = pk2h(p0[0], p0[1]);
            uint32_t a1 = pk2h(p0[2], p0[3]);
            uint32_t a2 = pk2h(p1[0], p1[1]);
            uint32_t a3 = pk2h(p1[2], p1[3]);
            #pragma unroll
            for (int nf = 0; nf < 16; nf++) {
                const int bw = (nf * 8 + g) * 36 + ks2 * 8 + t;
                uint32_t b0 = VtW[bw], b1 = VtW[bw + 4];
                mma_fp16(acc[nf], a0, a1, a2, a3, b0, b1);
            }
        }
        __syncthreads();
    }

    // ---- epilogue: normalize, write [B*S, D] (col = h*128 + d) ----
    const float rl0 = 1.0f / l0, rl1 = 1.0f / l1;
    const int b = bh >> 4, h = bh & 15;
    const size_t base0 = (size_t)(b * SEQ + s0 + qb + g) * DMODEL + h * HDIM;
    const size_t base1 = (size_t)(b * SEQ + s0 + qb + g + 8) * DMODEL + h * HDIM;
    #pragma unroll
    for (int nf = 0; nf < 16; nf++) {
        const int colb = nf * 8 + 2 * t;
        *(float2*)&Og[base0 + colb] = make_float2(acc[nf][0] * rl0, acc[nf][1] * rl0);
        *(float2*)&Og[base1 + colb] = make_float2(acc[nf][2] * rl1, acc[nf][3] * rl1);
    }
    #undef LOAD_TILE
}

// ---------------- launch ----------------
extern "C" void kernel_launch(void* const* d_in, const int* in_sizes, int n_in,
                              void* d_out, int out_size)
{
    const float* x     = (const float*)d_in[0];
    const float* w_qkv = (const float*)d_in[1];
    const float* w_out = (const float*)d_in[2];
    float* out = (float*)d_out;

    float *qkv, *Q, *K, *V, *attn;
    __half *wqkvT, *woutT;
    cudaGetSymbolAddress((void**)&qkv,   g_qkv);
    cudaGetSymbolAddress((void**)&Q,     g_Q);
    cudaGetSymbolAddress((void**)&K,     g_K);
    cudaGetSymbolAddress((void**)&V,     g_V);
    cudaGetSymbolAddress((void**)&attn,  g_attn);
    cudaGetSymbolAddress((void**)&wqkvT, g_wqkvT);
    cudaGetSymbolAddress((void**)&woutT, g_woutT);

    cudaFuncSetAttribute(attn_fp16_kernel, cudaFuncAttributeMaxDynamicSharedMemorySize,
                         ATT_BYTES);

    rope_table_kernel<<<SEQ, 64>>>();
    // pre-transpose weights to fp16 [N][K]
    transpose_fp16_kernel<<<dim3(D3 / 32, DMODEL / 32), dim3(32, 8)>>>(
        w_qkv, wqkvT, DMODEL, D3);
    transpose_fp16_kernel<<<dim3(DMODEL / 32, DMODEL / 32), dim3(32, 8)>>>(
        w_out, woutT, DMODEL, DMODEL);
    // qkv = x @ w_qkv   [4096,2048]x[2048,6144]  (fp16 m16n8k16, 2 CTAs/SM)
    fp16_mma_gemm<<<dim3(D3 / 128, MROWS / 128), 256>>>(
        x, wqkvT, qkv, MROWS, D3, DMODEL);
    // rope + split
    rope_split_kernel<<<MROWS, 256>>>(qkv, Q, K, V);
    // attention (fp16 flash: 2-mma QK with Q split, 1-mma PV)
    attn_fp16_kernel<<<dim3(SEQ / 128, BATCH * NHEADS), 256, ATT_BYTES>>>(Q, K, V, attn);
    // out = attn @ w_out  [4096,2048]x[2048,2048]  (fp16 m16n8k16, 2 CTAs/SM)
    fp16_mma_gemm<<<dim3(DMODEL / 128, MROWS / 128), 256>>>(
        attn, woutT, out, MROWS, DMODEL, DMODEL);
}

// round 17
// speedup vs baseline: 2.8227x; 1.0189x over previous
#include <cuda_runtime.h>
#include <cuda_bf16.h>
#include <cuda_fp16.h>
#include <cstddef>
#include <cstdint>

// Problem constants
#define BATCH 2
#define SEQ   2048
#define DMODEL 2048
#define NHEADS 16
#define HDIM  128
#define D3    (3 * DMODEL)
#define MROWS (BATCH * SEQ)   // 4096

// ---------------- scratch (no allocations allowed) ----------------
__device__ float g_qkv[(size_t)MROWS * D3];                       // [B*S, 3D]
__device__ float g_attn[(size_t)MROWS * DMODEL];                  // [B*S, D]
__device__ __align__(16) float g_cos[SEQ * 64];
__device__ __align__(16) float g_sin[SEQ * 64];
__device__ __half g_wqkvT[(size_t)D3 * DMODEL];                   // w_qkv^T fp16 [N][K]
__device__ __half g_woutT[(size_t)DMODEL * DMODEL];               // w_out^T fp16 [N][K]

// ---------------- helpers ----------------
// m16n8k16 fp16 warp MMA, fp32 accumulate (base PTX, sm_80+)
__device__ __forceinline__ void mma_fp16(float c[4],
                                         uint32_t a0, uint32_t a1, uint32_t a2, uint32_t a3,
                                         uint32_t b0, uint32_t b1) {
    asm volatile(
        "mma.sync.aligned.m16n8k16.row.col.f32.f16.f16.f32 "
        "{%0,%1,%2,%3}, {%4,%5,%6,%7}, {%8,%9}, {%0,%1,%2,%3};"
        : "+f"(c[0]), "+f"(c[1]), "+f"(c[2]), "+f"(c[3])
        : "r"(a0), "r"(a1), "r"(a2), "r"(a3), "r"(b0), "r"(b1));
}

// pack two fp32 -> fp16x2 reg (lo_elem -> bits[15:0], hi_elem -> bits[31:16])
__device__ __forceinline__ uint32_t pk2h(float lo_elem, float hi_elem) {
    uint32_t r;
    asm("cvt.rn.f16x2.f32 %0, %1, %2;" : "=r"(r) : "f"(hi_elem), "f"(lo_elem));
    return r;
}

// ---------------- RoPE table ----------------
__global__ void rope_table_kernel() {
    int s = blockIdx.x;
    int j = threadIdx.x;            // 0..63
    float inv = powf(10000.0f, -(float)j / 64.0f);
    float ang = (float)s * inv;
    g_cos[s * 64 + j] = cosf(ang);
    g_sin[s * 64 + j] = sinf(ang);
}

// ---------------- weight transpose: W[K][N] fp32 -> WT[N][K] fp16 ----------------
__global__ __launch_bounds__(256) void transpose_fp16_kernel(
    const float* __restrict__ W, __half* __restrict__ WT, int K_, int N)
{
    __shared__ float t[32][33];
    const int tx = threadIdx.x, ty = threadIdx.y;   // (32, 8)
    const int n0 = blockIdx.x * 32, k0 = blockIdx.y * 32;
    #pragma unroll
    for (int j = 0; j < 4; j++)
        t[ty + 8 * j][tx] = W[(size_t)(k0 + ty + 8 * j) * N + n0 + tx];
    __syncthreads();
    #pragma unroll
    for (int j = 0; j < 4; j++)
        WT[(size_t)(n0 + ty + 8 * j) * K_ + k0 + tx] = __float2half(t[tx][ty + 8 * j]);
}

// ================= fp16 m16n8k16 GEMM: C[M,N] = A[M,K] * B[K,N] =================
// (unchanged from R14, known-good, 2 CTAs/SM)
#define GF_AST 40
#define GF_ELEMS (128 * GF_AST)            // 5120 halfs per tile buffer

__global__ __launch_bounds__(256, 2) void fp16_mma_gemm(
    const float* __restrict__ A, const __half* __restrict__ Bt, float* __restrict__ C,
    int M, int N, int K_)
{
    __shared__ __half Asm[2][GF_ELEMS];
    __shared__ __half Bsm[2][GF_ELEMS];

    const int tid = threadIdx.x;
    const int wid = tid >> 5, lane = tid & 31;
    const int g = lane >> 2, t = lane & 3;
    const int wm = wid >> 2, wn = wid & 3;
    const int m0 = blockIdx.y * 128, n0 = blockIdx.x * 128;
    const int mbase = wm * 64, nbase = wn * 32;

    float4 apref[4];
    uint4  bpref[2];

    #define LOADG(kt) do { \
        _Pragma("unroll") \
        for (int i = 0; i < 4; i++) { \
            int f4 = tid + i * 256; \
            int r = f4 >> 3, c = (f4 & 7) << 2; \
            apref[i] = *(const float4*)&A[(size_t)(m0 + r) * K_ + (kt) * 32 + c]; \
        } \
        _Pragma("unroll") \
        for (int i = 0; i < 2; i++) { \
            int idx = tid + i * 256; \
            int r = idx >> 2, c8 = (idx & 3) << 3; \
            bpref[i] = *(const uint4*)&Bt[(size_t)(n0 + r) * K_ + (kt) * 32 + c8]; \
        } \
    } while (0)

    #define STORES(buf) do { \
        _Pragma("unroll") \
        for (int i = 0; i < 4; i++) { \
            int f4 = tid + i * 256; \
            int r = f4 >> 3, c = (f4 & 7) << 2; \
            __half2 p0 = __floats2half2_rn(apref[i].x, apref[i].y); \
            __half2 p1 = __floats2half2_rn(apref[i].z, apref[i].w); \
            uint2 pk; pk.x = *(uint32_t*)&p0; pk.y = *(uint32_t*)&p1; \
            *(uint2*)&Asm[buf][r * GF_AST + c] = pk; \
        } \
        _Pragma("unroll") \
        for (int i = 0; i < 2; i++) { \
            int idx = tid + i * 256; \
            int r = idx >> 2, c8 = (idx & 3) << 3; \
            *(uint4*)&Bsm[buf][r * GF_AST + c8] = bpref[i]; \
        } \
    } while (0)

    float acc[4][4][4];
    #pragma unroll
    for (int mf = 0; mf < 4; mf++)
        #pragma unroll
        for (int nf = 0; nf < 4; nf++)
            #pragma unroll
            for (int q = 0; q < 4; q++) acc[mf][nf][q] = 0.0f;

    const int KT = K_ / 32;
    LOADG(0);
    STORES(0);
    __syncthreads();

    for (int kt = 0; kt < KT; kt++) {
        const int buf = kt & 1;
        if (kt + 1 < KT) LOADG(kt + 1);

        const uint32_t* Aw = (const uint32_t*)Asm[buf];
        const uint32_t* Bw = (const uint32_t*)Bsm[buf];
        #pragma unroll
        for (int ks = 0; ks < 2; ks++) {
            const int kw = ks * 8;          // word offset of k16 step
            uint32_t af[4][4];
            #pragma unroll
            for (int mf = 0; mf < 4; mf++) {
                const int row = mbase + mf * 16 + g;
                const int base = row * 20 + kw + t;
                af[mf][0] = Aw[base];
                af[mf][1] = Aw[base + 8 * 20];
                af[mf][2] = Aw[base + 4];
                af[mf][3] = Aw[base + 8 * 20 + 4];
            }
            uint32_t bfr[4][2];
            #pragma unroll
            for (int nf = 0; nf < 4; nf++) {
                const int col = nbase + nf * 8 + g;
                const int base = col * 20 + kw + t;
                bfr[nf][0] = Bw[base];
                bfr[nf][1] = Bw[base + 4];
            }
            #pragma unroll
            for (int mf = 0; mf < 4; mf++)
                #pragma unroll
                for (int nf = 0; nf < 4; nf++)
                    mma_fp16(acc[mf][nf], af[mf][0], af[mf][1], af[mf][2], af[mf][3],
                             bfr[nf][0], bfr[nf][1]);
        }

        if (kt + 1 < KT) {
            STORES(buf ^ 1);
            __syncthreads();
        }
    }

    #pragma unroll
    for (int mf = 0; mf < 4; mf++) {
        #pragma unroll
        for (int nf = 0; nf < 4; nf++) {
            const int row = m0 + mbase + mf * 16 + g;
            const int col = n0 + nbase + nf * 8 + 2 * t;
            *(float2*)&C[(size_t)row * N + col] =
                make_float2(acc[mf][nf][0], acc[mf][nf][1]);
            *(float2*)&C[(size_t)(row + 8) * N + col] =
                make_float2(acc[mf][nf][2], acc[mf][nf][3]);
        }
    }
    #undef LOADG
    #undef STORES
}

// ============ fp16 flash attention with fused RoPE (mma.sync m16n8k16) ============
// Reads Q/K/V directly from qkv[B*S, 3D], applying RoPE to Q,K in the loaders.
// q-tile 128, kv-tile 64, 256 threads = 8 warps; warp w owns q rows w*16..w*16+15
// and ALL 64 kv columns -> warp-local softmax, P stays in registers.
// QK^T: 1-mma fp16 (plain Q, plain K).  PV: 1-mma fp16 (P from C-frags, plain V).
// Q/K rows: 128 d-elems, stride QST=136 (68 words = 4 mod 32, conflict-free).
// VT rows: 64 kv-elems, stride VST=72 (36 words, same property). K/VT double-buffered.
#define QST 136
#define VST 72
#define S_Q   0
#define S_KB  (128 * QST)                        // 17408
#define S_K(b)  (S_KB + (b) * 64 * QST)
#define S_VTB (S_KB + 2 * 64 * QST)              // 34816
#define S_VT(b) (S_VTB + (b) * 128 * VST)
#define ATT_ELEMS (S_VTB + 2 * 128 * VST)        // 53248 halfs
#define ATT_BYTES (ATT_ELEMS * 2)                // 106496

__global__ __launch_bounds__(256, 1) void attn_fp16_kernel(
    const float* __restrict__ qkv, float* __restrict__ Og)
{
    extern __shared__ __half smh[];
    const int tid = threadIdx.x;
    const int w = tid >> 5, lane = tid & 31;
    const int g = lane >> 2, t = tid & 3;
    const int qb = w * 16;
    const int bh = blockIdx.y;
    const int b = bh >> 4, h = bh & 15;
    const int s0 = blockIdx.x * 128;
    const float* base = qkv + (size_t)b * SEQ * D3;
    const int qoff = h * HDIM;
    const int koff = DMODEL + h * HDIM;
    const int voff = 2 * DMODEL + h * HDIM;
    const float SCL2E = 0.08838834764831845f * 1.4426950408889634f; // 1/sqrt(128)*log2e

    // ---- load Q tile (128 x 128) with RoPE, fp16 ----
    #pragma unroll
    for (int i = 0; i < 16; i++) {
        int f4 = tid + i * 256;                 // 0..4095
        int r = f4 >> 5, c4 = (f4 & 31) << 2;
        int s_abs = s0 + r;
        const float* rowp = base + (size_t)s_abs * D3 + qoff;
        float4 v = *(const float4*)(rowp + c4);
        float4 p = *(const float4*)(rowp + (c4 ^ 64));
        int j = c4 & 63;
        float4 cs = *(const float4*)&g_cos[s_abs * 64 + j];
        float4 sn = *(const float4*)&g_sin[s_abs * 64 + j];
        float sg = (c4 < 64) ? -1.0f : 1.0f;
        float q0 = v.x * cs.x + sg * p.x * sn.x;
        float q1 = v.y * cs.y + sg * p.y * sn.y;
        float q2 = v.z * cs.z + sg * p.z * sn.z;
        float q3 = v.w * cs.w + sg * p.w * sn.w;
        *(__half2*)&smh[S_Q + r * QST + c4]     = __floats2half2_rn(q0, q1);
        *(__half2*)&smh[S_Q + r * QST + c4 + 2] = __floats2half2_rn(q2, q3);
    }

    // ---- tile loader: K [64][128] with RoPE + V transposed to [d][kv], fp16 ----
    #define LOAD_TILE(kt, bb) do { \
        const int ks0_ = (kt) * 64; \
        _Pragma("unroll") \
        for (int i = 0; i < 8; i++) { \
            int f4 = tid + i * 256; \
            int r = f4 >> 5, c4 = (f4 & 31) << 2; \
            int s_abs = ks0_ + r; \
            const float* rowp = base + (size_t)s_abs * D3 + koff; \
            float4 v = *(const float4*)(rowp + c4); \
            float4 p = *(const float4*)(rowp + (c4 ^ 64)); \
            int j = c4 & 63; \
            float4 cs = *(const float4*)&g_cos[s_abs * 64 + j]; \
            float4 sn = *(const float4*)&g_sin[s_abs * 64 + j]; \
            float sg = (c4 < 64) ? -1.0f : 1.0f; \
            float k0 = v.x * cs.x + sg * p.x * sn.x; \
            float k1 = v.y * cs.y + sg * p.y * sn.y; \
            float k2 = v.z * cs.z + sg * p.z * sn.z; \
            float k3 = v.w * cs.w + sg * p.w * sn.w; \
            *(__half2*)&smh[S_K(bb) + r * QST + c4]     = __floats2half2_rn(k0, k1); \
            *(__half2*)&smh[S_K(bb) + r * QST + c4 + 2] = __floats2half2_rn(k2, k3); \
        } \
        _Pragma("unroll") \
        for (int it = 0; it < 32; it++) { \
            int kv = w + 8 * (it >> 2); \
            int d  = ((it & 3) << 5) + lane; \
            float vv = base[(size_t)(ks0_ + kv) * D3 + voff + d]; \
            smh[S_VT(bb) + d * VST + kv] = __float2half(vv); \
        } \
    } while (0)

    LOAD_TILE(0, 0);
    __syncthreads();

    float m0 = -1e30f, m1 = -1e30f, l0 = 0.0f, l1 = 0.0f;
    float acc[16][4];
    #pragma unroll
    for (int nf = 0; nf < 16; nf++)
        #pragma unroll
        for (int q = 0; q < 4; q++) acc[nf][q] = 0.0f;

    const uint32_t* Qw = (const uint32_t*)(smh + S_Q);

    for (int kt = 0; kt < SEQ / 64; kt++) {
        const int buf = kt & 1;
        if (kt + 1 < SEQ / 64) LOAD_TILE(kt + 1, buf ^ 1);

        const uint32_t* Kw  = (const uint32_t*)(smh + S_K(buf));
        const uint32_t* VtW = (const uint32_t*)(smh + S_VT(buf));

        // ---- S = Q K^T : 1-mma fp16, 16q x 64kv per warp ----
        float sfr[8][4];
        #pragma unroll
        for (int nf = 0; nf < 8; nf++)
            #pragma unroll
            for (int q = 0; q < 4; q++) sfr[nf][q] = 0.0f;

        #pragma unroll
        for (int ks = 0; ks < 8; ks++) {
            const int aw = (qb + g) * 68 + ks * 8 + t;
            const int aw8 = aw + 8 * 68;
            uint32_t a0 = Qw[aw],     a1 = Qw[aw8];
            uint32_t a2 = Qw[aw + 4], a3 = Qw[aw8 + 4];
            #pragma unroll
            for (int nf = 0; nf < 8; nf++) {
                const int bw = (nf * 8 + g) * 68 + ks * 8 + t;
                uint32_t b0 = Kw[bw], b1 = Kw[bw + 4];
                mma_fp16(sfr[nf], a0, a1, a2, a3, b0, b1);
            }
        }

        // ---- warp-local online softmax (log2 domain) ----
        #pragma unroll
        for (int nf = 0; nf < 8; nf++)
            #pragma unroll
            for (int q = 0; q < 4; q++) sfr[nf][q] *= SCL2E;

        float mx0 = -1e30f, mx1 = -1e30f;
        #pragma unroll
        for (int nf = 0; nf < 8; nf++) {
            mx0 = fmaxf(mx0, fmaxf(sfr[nf][0], sfr[nf][1]));
            mx1 = fmaxf(mx1, fmaxf(sfr[nf][2], sfr[nf][3]));
        }
        mx0 = fmaxf(mx0, __shfl_xor_sync(0xffffffffu, mx0, 1));
        mx0 = fmaxf(mx0, __shfl_xor_sync(0xffffffffu, mx0, 2));
        mx1 = fmaxf(mx1, __shfl_xor_sync(0xffffffffu, mx1, 1));
        mx1 = fmaxf(mx1, __shfl_xor_sync(0xffffffffu, mx1, 2));

        float mn0 = fmaxf(m0, mx0), mn1 = fmaxf(m1, mx1);
        float corr0 = exp2f(m0 - mn0), corr1 = exp2f(m1 - mn1);
        m0 = mn0; m1 = mn1;

        float sum0 = 0.0f, sum1 = 0.0f;
        #pragma unroll
        for (int nf = 0; nf < 8; nf++) {
            sfr[nf][0] = exp2f(sfr[nf][0] - mn0);
            sfr[nf][1] = exp2f(sfr[nf][1] - mn0);
            sfr[nf][2] = exp2f(sfr[nf][2] - mn1);
            sfr[nf][3] = exp2f(sfr[nf][3] - mn1);
            sum0 += sfr[nf][0] + sfr[nf][1];
            sum1 += sfr[nf][2] + sfr[nf][3];
        }
        sum0 += __shfl_xor_sync(0xffffffffu, sum0, 1);
        sum0 += __shfl_xor_sync(0xffffffffu, sum0, 2);
        sum1 += __shfl_xor_sync(0xffffffffu, sum1, 1);
        sum1 += __shfl_xor_sync(0xffffffffu, sum1, 2);
        l0 = l0 * corr0 + sum0;
        l1 = l1 * corr1 + sum1;

        #pragma unroll
        for (int nf = 0; nf < 16; nf++) {
            acc[nf][0] *= corr0; acc[nf][1] *= corr0;
            acc[nf][2] *= corr1; acc[nf][3] *= corr1;
        }

        // ---- O += P V : 1-mma fp16, P packed straight from C-frags ----
        #pragma unroll
        for (int ks2 = 0; ks2 < 4; ks2++) {
            const float* p0 = sfr[2 * ks2];
            const float* p1 = sfr[2 * ks2 + 1];
            uint32_t a0 = pk2h(p0[0], p0[1]);
            uint32_t a1 = pk2h(p0[2], p0[3]);
            uint32_t a2 = pk2h(p1[0], p1[1]);
            uint32_t a3 = pk2h(p1[2], p1[3]);
            #pragma unroll
            for (int nf = 0; nf < 16; nf++) {
                const int bw = (nf * 8 + g) * 36 + ks2 * 8 + t;
                uint32_t b0 = VtW[bw], b1 = VtW[bw + 4];
                mma_fp16(acc[nf], a0, a1, a2, a3, b0, b1);
            }
        }
        __syncthreads();
    }

    // ---- epilogue: normalize, write [B*S, D] (col = h*128 + d) ----
    const float rl0 = 1.0f / l0, rl1 = 1.0f / l1;
    const size_t base0 = (size_t)(b * SEQ + s0 + qb + g) * DMODEL + h * HDIM;
    const size_t base1 = (size_t)(b * SEQ + s0 + qb + g + 8) * DMODEL + h * HDIM;
    #pragma unroll
    for (int nf = 0; nf < 16; nf++) {
        const int colb = nf * 8 + 2 * t;
        *(float2*)&Og[base0 + colb] = make_float2(acc[nf][0] * rl0, acc[nf][1] * rl0);
        *(float2*)&Og[base1 + colb] = make_float2(acc[nf][2] * rl1, acc[nf][3] * rl1);
    }
    #undef LOAD_TILE
}

// ---------------- launch ----------------
extern "C" void kernel_launch(void* const* d_in, const int* in_sizes, int n_in,
                              void* d_out, int out_size)
{
    const float* x     = (const float*)d_in[0];
    const float* w_qkv = (const float*)d_in[1];
    const float* w_out = (const float*)d_in[2];
    float* out = (float*)d_out;

    float *qkv, *attn;
    __half *wqkvT, *woutT;
    cudaGetSymbolAddress((void**)&qkv,   g_qkv);
    cudaGetSymbolAddress((void**)&attn,  g_attn);
    cudaGetSymbolAddress((void**)&wqkvT, g_wqkvT);
    cudaGetSymbolAddress((void**)&woutT, g_woutT);

    cudaFuncSetAttribute(attn_fp16_kernel, cudaFuncAttributeMaxDynamicSharedMemorySize,
                         ATT_BYTES);

    rope_table_kernel<<<SEQ, 64>>>();
    // pre-transpose weights to fp16 [N][K]
    transpose_fp16_kernel<<<dim3(D3 / 32, DMODEL / 32), dim3(32, 8)>>>(
        w_qkv, wqkvT, DMODEL, D3);
    transpose_fp16_kernel<<<dim3(DMODEL / 32, DMODEL / 32), dim3(32, 8)>>>(
        w_out, woutT, DMODEL, DMODEL);
    // qkv = x @ w_qkv   [4096,2048]x[2048,6144]  (fp16 m16n8k16, 2 CTAs/SM)
    fp16_mma_gemm<<<dim3(D3 / 128, MROWS / 128), 256>>>(
        x, wqkvT, qkv, MROWS, D3, DMODEL);
    // attention (fp16 flash, RoPE fused into loaders, 1-mma QK / 1-mma PV)
    attn_fp16_kernel<<<dim3(SEQ / 128, BATCH * NHEADS), 256, ATT_BYTES>>>(qkv, attn);
    // out = attn @ w_out  [4096,2048]x[2048,2048]  (fp16 m16n8k16, 2 CTAs/SM)
    fp16_mma_gemm<<<dim3(DMODEL / 128, MROWS / 128), 256>>>(
        attn, woutT, out, MROWS, DMODEL, DMODEL);
}